// round 17
// baseline (speedup 1.0000x reference)
#include <cuda_runtime.h>
#include <cstdint>

// Problem constants
#define Bc 16
#define Sc 24
#define Lc 128
#define Dc 768
#define Ac 8
#define Tc 8
#define SLOTS_PER_TYPE 8
#define MAXPAIRS_T (SLOTS_PER_TYPE * Lc)

#define LSPLIT 4
#define LROWS (Lc / LSPLIT)       // 32 rows per A-block
#define NTHR 192                  // Dc/4 float4 columns
#define GRP 7                     // 3 B-blocks + 4 A-blocks per bs
#define NBLK (Bc * Sc * GRP)      // 2688
#define BB 6                      // B gather batch (rows in flight)

// mean-pool partials, pre-scaled by 1/count (static device global: allowed)
__device__ float        g_scratch[LSPLIT][Bc * Sc * Dc];
// arrival counter per bs; never reset — modulo-LSPLIT selects last arriver.
__device__ unsigned int g_counter[Bc * Sc];

__global__ __launch_bounds__(NTHR, 6)
void srl_fused_kernel(const float* __restrict__ emb,
                      const int* __restrict__ masks,
                      const int* __restrict__ sids,
                      const int* __restrict__ pred_ids,
                      const int* __restrict__ arg0_ids,
                      const int* __restrict__ arg1_ids,
                      float* __restrict__ out)
{
    const int bid = blockIdx.x;
    const int tid = threadIdx.x;
    const int g   = bid / GRP;     // bs
    const int r   = bid % GRP;     // 0..2: B-block (type r); 3..6: A-block (lh r-3)

    if (r >= 3) {
        // ===================== A-block: mean-pool partial ====================
        __shared__ float s_maskf[Lc];
        __shared__ float s_wcnt[4];
        __shared__ int   s_last;

        const int bs   = g;
        const int lh   = r - 3;
        const int lane = tid & 31;
        const int wid  = tid >> 5;

        if (tid < Lc) {
            float m = (float)masks[bs * Lc + tid];
            s_maskf[tid] = m;
            float c = m;
            #pragma unroll
            for (int off = 16; off; off >>= 1)
                c += __shfl_xor_sync(0xffffffffu, c, off);
            if (lane == 0) s_wcnt[wid] = c;
        }
        __syncthreads();
        const float inv = 1.0f / fmaxf(s_wcnt[0] + s_wcnt[1] +
                                       s_wcnt[2] + s_wcnt[3], 1.0f);

        const int lbase = lh * LROWS;
        const float4* ep = (const float4*)(emb + (size_t)bs * Lc * Dc) + tid;

        float4 acc = make_float4(0.f, 0.f, 0.f, 0.f);

        #pragma unroll 1
        for (int lb = 0; lb < LROWS; lb += 8) {
            float4 v[8];
            #pragma unroll
            for (int i = 0; i < 8; i++)
                v[i] = ep[(size_t)(lbase + lb + i) * (Dc / 4)];
            #pragma unroll
            for (int i = 0; i < 8; i++) {
                float mf = s_maskf[lbase + lb + i];
                acc.x = fmaf(v[i].x, mf, acc.x);
                acc.y = fmaf(v[i].y, mf, acc.y);
                acc.z = fmaf(v[i].z, mf, acc.z);
                acc.w = fmaf(v[i].w, mf, acc.w);
            }
        }

        float4* o = (float4*)(&g_scratch[lh][0] + (size_t)bs * Dc) + tid;
        *o = make_float4(acc.x * inv, acc.y * inv, acc.z * inv, acc.w * inv);

        // ---- last-arriving A-block for this bs combines the 4 partials
        __threadfence();
        __syncthreads();
        if (tid == 0) {
            unsigned int old = atomicAdd(&g_counter[bs], 1u);
            s_last = ((old & (LSPLIT - 1)) == (LSPLIT - 1));
        }
        __syncthreads();
        if (s_last) {
            __threadfence();   // acquire: see all partials
            const float4* p0 = (const float4*)(&g_scratch[0][0] + (size_t)bs * Dc) + tid;
            const float4* p1 = (const float4*)(&g_scratch[1][0] + (size_t)bs * Dc) + tid;
            const float4* p2 = (const float4*)(&g_scratch[2][0] + (size_t)bs * Dc) + tid;
            const float4* p3 = (const float4*)(&g_scratch[3][0] + (size_t)bs * Dc) + tid;
            float4 a = *p0, b = *p1, c = *p2, d = *p3;
            a.x = ((a.x + b.x) + c.x) + d.x;
            a.y = ((a.y + b.y) + c.y) + d.y;
            a.z = ((a.z + b.z) + c.z) + d.z;
            a.w = ((a.w + b.w) + c.w) + d.w;
            float4* oo = (float4*)(out + (size_t)bs * Dc) + tid;
            *oo = a;
        }
        return;
    }

    // ======================= B-block: slot gather ============================
    __shared__ int            s_sid[Lc];
    __shared__ int            s_argids[SLOTS_PER_TYPE * Tc];
    __shared__ int            s_cnt[SLOTS_PER_TYPE * Tc];
    __shared__ int            s_chosen[SLOTS_PER_TYPE];
    __shared__ float          s_invc[SLOTS_PER_TYPE];
    __shared__ int            s_nm[SLOTS_PER_TYPE];
    __shared__ int            s_off[SLOTS_PER_TYPE + 1];
    __shared__ unsigned int   s_bm[SLOTS_PER_TYPE][4];
    __shared__ unsigned short s_pairs[MAXPAIRS_T];

    const int bs   = g;
    const int type = r;
    const int lane = tid & 31;
    const int wid  = tid >> 5;

    const size_t OFF0 = (size_t)Bc * Sc * Dc;
    const size_t ASZ  = (size_t)Bc * Sc * Ac * Dc;

    // stage metadata
    if (tid < Lc) s_sid[tid] = sids[bs * Lc + tid];
    const int* src = (type == 0) ? pred_ids : (type == 1) ? arg0_ids : arg1_ids;
    if (tid < SLOTS_PER_TYPE * Tc) {
        int a = tid / Tc, t = tid % Tc;
        s_argids[tid] = src[(bs * Ac + a) * Tc + t];
    }
    __syncthreads();

    // per-(slot,t) match counts
    if (tid < SLOTS_PER_TYPE * Tc) {
        int id = s_argids[tid];
        int c = 0;
        if (id != 0) {
            #pragma unroll 8
            for (int l = 0; l < Lc; l++) c += (s_sid[l] == id);
        }
        s_cnt[tid] = c;
    }
    __syncthreads();

    // per-slot chosen id / count
    if (tid < SLOTS_PER_TYPE) {
        int chosen = -1, nm = 0;
        float invc = 1.0f;
        #pragma unroll
        for (int t = Tc - 1; t >= 0; t--) {
            int c = s_cnt[tid * Tc + t];
            if (c > 0) { chosen = s_argids[tid * Tc + t]; nm = c;
                         invc = 1.0f / (float)c; break; }
        }
        s_chosen[tid] = chosen;
        s_invc[tid]   = invc;
        s_nm[tid]     = nm;
    }
    __syncthreads();

    // parallel ballot: which l positions match each slot's chosen id
    if (wid < 4) {
        int sid = s_sid[tid];
        #pragma unroll
        for (int s = 0; s < SLOTS_PER_TYPE; s++) {
            unsigned int bm = __ballot_sync(0xffffffffu, sid == s_chosen[s]);
            if (lane == 0) s_bm[s][wid] = bm;
        }
    }
    if (tid == 0) {
        int o = 0;
        #pragma unroll
        for (int s = 0; s < SLOTS_PER_TYPE; s++) { s_off[s] = o; o += s_nm[s]; }
        s_off[SLOTS_PER_TYPE] = o;
    }
    __syncthreads();

    // parallel pair-list build (slot-major, l-ordered => deterministic)
    if (wid < 4) {
        int sid = s_sid[tid];
        const unsigned int ltmask = (lane == 31) ? 0x7fffffffu
                                                 : ((1u << lane) - 1u);
        #pragma unroll
        for (int s = 0; s < SLOTS_PER_TYPE; s++) {
            if (sid == s_chosen[s]) {
                int rank = __popc(s_bm[s][wid] & ltmask);
                #pragma unroll
                for (int w = 0; w < 4; w++)
                    if (w < wid) rank += __popc(s_bm[s][w]);
                s_pairs[s_off[s] + rank] = (unsigned short)((s << 8) | tid);
            }
        }
    }
    __syncthreads();

    const int npairs = s_off[SLOTS_PER_TYPE];

    // zero outputs for empty slots
    #pragma unroll
    for (int s = 0; s < SLOTS_PER_TYPE; s++) {
        if (s_nm[s] == 0) {
            float4* o = (float4*)(out + OFF0 + (size_t)type * ASZ
                                  + ((size_t)bs * Ac + s) * Dc) + tid;
            *o = make_float4(0.f, 0.f, 0.f, 0.f);
        }
    }

    // batched gather: BB rows in flight, flush on slot change
    const float4* ebase = (const float4*)(emb + (size_t)bs * Lc * Dc) + tid;
    float4 acc = make_float4(0.f, 0.f, 0.f, 0.f);
    int cur = -1;

    for (int p0 = 0; p0 < npairs; p0 += BB) {
        const int nb = min(BB, npairs - p0);
        float4 v[BB];
        int    sl[BB];
        #pragma unroll
        for (int i = 0; i < BB; i++) {
            if (i < nb) {
                int pr = s_pairs[p0 + i];
                sl[i] = pr >> 8;
                v[i]  = ebase[(size_t)(pr & 255) * (Dc / 4)];
            }
        }
        #pragma unroll
        for (int i = 0; i < BB; i++) {
            if (i < nb) {
                if (sl[i] != cur) {
                    if (cur >= 0) {
                        float inv = s_invc[cur];
                        float4* o = (float4*)(out + OFF0 + (size_t)type * ASZ
                                              + ((size_t)bs * Ac + cur) * Dc) + tid;
                        *o = make_float4(acc.x * inv, acc.y * inv,
                                         acc.z * inv, acc.w * inv);
                    }
                    cur = sl[i];
                    acc = v[i];
                } else {
                    acc.x += v[i].x; acc.y += v[i].y;
                    acc.z += v[i].z; acc.w += v[i].w;
                }
            }
        }
    }
    if (cur >= 0) {
        float inv = s_invc[cur];
        float4* o = (float4*)(out + OFF0 + (size_t)type * ASZ
                              + ((size_t)bs * Ac + cur) * Dc) + tid;
        *o = make_float4(acc.x * inv, acc.y * inv, acc.z * inv, acc.w * inv);
    }
}

extern "C" void kernel_launch(void* const* d_in, const int* in_sizes, int n_in,
                              void* d_out, int out_size)
{
    const float* emb   = (const float*)d_in[0];  // [B,S,L,D] f32
    const int*   masks = (const int*)d_in[1];    // [B,S,L] i32
    const int*   sids  = (const int*)d_in[2];    // [B,S,L] i32
    const int*   pred  = (const int*)d_in[3];    // [B,S,A,T] i32
    const int*   a0    = (const int*)d_in[4];    // [B,S,A,T] i32
    const int*   a1    = (const int*)d_in[5];    // [B,S,A,T] i32
    float*       out   = (float*)d_out;

    srl_fused_kernel<<<NBLK, NTHR>>>(emb, masks, sids, pred, a0, a1, out);
}